// round 13
// baseline (speedup 1.0000x reference)
#include <cuda_runtime.h>
#include <cuda_fp16.h>
#include <cstdint>

// ---------------- problem constants ----------------
#define DD    96
#define DSC   48
#define CH    64
#define ND    (DSC*DSC*DSC)     // 110592 coarse voxels
#define MT    64                // M tile per CTA
#define NCTA  (ND/MT)           // 1728
#define NCHUNK 8

// fp16 A rows padded to 72 fp16 (144 B) for conflict-free ldmatrix
#define APITCH 72
#define APB    (APITCH*2)
// fp32 staging rows padded to 272 B (256 + 16) to break LDS bank overlap
#define SPITCH 272

// ---------------- smem layout (bytes) ----------------
#define SM_BROW 0                          // 64 ints
#define OFF_F0  512
#define OFF_F1  (OFF_F0 + MT*APB)          // +9216
#define OFF_S0  (OFF_F1 + MT*APB)          // fp32 staging 0
#define OFF_S1  (OFF_S0 + MT*SPITCH)       // fp32 staging 1
#define SMEM_TOTAL (OFF_S1 + MT*SPITCH)    // 53760

// W pre-packed in m16n8k16 B-fragment order:
// idx = (((s*4 + kb)*8 + jn)*32 + lane)*2 + r
// element: k = s*64 + kb*16 + r*8 + (lane%4)*2 + h,  n = jn*8 + lane/4
__device__ __align__(16) uint32_t g_wf[NCHUNK * 4 * 8 * 32 * 2];   // 64 KB

// ---------------- helpers ----------------
__device__ __forceinline__ uint32_t smem_u32(const void* p) {
    uint32_t a;
    asm("{ .reg .u64 t; cvta.to.shared.u64 t, %1; cvt.u32.u64 %0, t; }" : "=r"(a) : "l"(p));
    return a;
}
__device__ __forceinline__ void ldm_x4(uint32_t* r, uint32_t addr) {
    asm volatile("ldmatrix.sync.aligned.m8n8.x4.shared.b16 {%0,%1,%2,%3}, [%4];"
        : "=r"(r[0]), "=r"(r[1]), "=r"(r[2]), "=r"(r[3]) : "r"(addr));
}
__device__ __forceinline__ void mma_fp16(float* d, const uint32_t* a, const uint32_t* b) {
    asm volatile("mma.sync.aligned.m16n8k16.row.col.f32.f16.f16.f32 "
        "{%0,%1,%2,%3}, {%4,%5,%6,%7}, {%8,%9}, {%0,%1,%2,%3};"
        : "+f"(d[0]), "+f"(d[1]), "+f"(d[2]), "+f"(d[3])
        : "r"(a[0]), "r"(a[1]), "r"(a[2]), "r"(a[3]), "r"(b[0]), "r"(b[1]));
}
__device__ __forceinline__ uint32_t cvt2(float a, float b) {
    __half2 h = __floats2half2_rn(a, b);
    return *(uint32_t*)&h;
}
__device__ __forceinline__ void cp16(uint32_t dst, const float* src) {
    asm volatile("{ .reg .u64 g; cvta.to.global.u64 g, %1; "
                 "cp.async.cg.shared.global [%0], [g], 16; }"
                 :: "r"(dst), "l"(src) : "memory");
}
#define CP_COMMIT() asm volatile("cp.async.commit_group;" ::: "memory")
#define CP_WAIT1()  asm volatile("cp.async.wait_group 1;" ::: "memory")
#define CP_WAIT0()  asm volatile("cp.async.wait_group 0;" ::: "memory")

// ---------------- pre-kernel: W -> fp16 fragment-order ----------------
__global__ void conv_wf_kernel(const float* __restrict__ w) {
    int idx = blockIdx.x * blockDim.x + threadIdx.x;   // 0..16383
    int r  = idx & 1;
    int l  = (idx >> 1) & 31;
    int jn = (idx >> 6) & 7;
    int kb = (idx >> 9) & 3;
    int s  = idx >> 11;
    int k  = s * 64 + kb * 16 + r * 8 + (l & 3) * 2;
    int n  = jn * 8 + (l >> 2);
    g_wf[idx] = cvt2(w[k * 64 + n], w[(k + 1) * 64 + n]);
}

// ---------------- main kernel: 128 threads, 4 warps (2m x 2n), tile M32 x N32 ----
extern __shared__ char smem[];

__global__ void __launch_bounds__(128, 4)
ds_fp16_mma_kernel(const float* __restrict__ in_data, float* __restrict__ out) {
    const int tid = threadIdx.x;
    const int wid = tid >> 5;
    const int l   = tid & 31;
    const int wm  = wid & 1;      // m-tile of warp (rows wm*32..+32)
    const int wn  = wid >> 1;     // n-tile of warp (cols wn*32..+32)
    const uint32_t sbase = smem_u32(smem);

    int* baseRow = (int*)(smem + SM_BROW);
    if (tid < MT) {
        int dm  = blockIdx.x * MT + tid;
        int di  = dm / (DSC * DSC);
        int rem = dm - di * DSC * DSC;
        int dj  = rem / DSC;
        int dk  = rem - dj * DSC;
        baseRow[tid] = ((2 * di) * DD + 2 * dj) * DD + 2 * dk;
    }
    __syncthreads();

    // loader role: 16 threads per row, one float4 each -> fully coalesced lines
    const int q  = tid & 15;           // float4 index within 256B row
    const int rg = tid >> 4;           // 0..7; rows rg + g*8
    const float* src0[8];
    #pragma unroll
    for (int g = 0; g < 8; g++)
        src0[g] = in_data + (size_t)baseRow[rg + g * 8] * CH + q * 4;

    // per-thread staging addresses (same for both buffers, + buffer offset)
    const uint32_t stgOff = (uint32_t)(rg * SPITCH + q * 16);

    // ldmatrix A address components
    const uint32_t aOff0 = (uint32_t)((wm * 32 + (l & 15)) * APITCH + (l >> 4) * 8) * 2;
    const uint32_t aOff1 = aOff0 + 16 * APB;

    float acc0[4][4], acc1[4][4];
    #pragma unroll
    for (int n = 0; n < 4; n++)
        #pragma unroll
        for (int i = 0; i < 4; i++) { acc0[n][i] = 0.0f; acc1[n][i] = 0.0f; }

    const uint2* wfrag = (const uint2*)g_wf;   // index: ((s*4+kb)*8 + jn)*32 + lane

    // ---- prolog: stage chunks 0 and 1 via cp.async ----
    {
        #pragma unroll
        for (int g = 0; g < 8; g++)
            cp16(sbase + OFF_S0 + stgOff + g * (8 * SPITCH), src0[g]);       // octant 0
        CP_COMMIT();
        #pragma unroll
        for (int g = 0; g < 8; g++)
            cp16(sbase + OFF_S1 + stgOff + g * (8 * SPITCH), src0[g] + CH);  // octant s=1: offs=1 row
        CP_COMMIT();
    }

    for (int s = 0; s < NCHUNK; s++) {
        const uint32_t fbase = sbase + ((s & 1) ? OFF_F1 : OFF_F0);
        const uint32_t stg   = sbase + ((s & 1) ? OFF_S1 : OFF_S0) + stgOff;

        // ---- chunk s staged? (own-thread data only: no barrier needed) ----
        if (s == NCHUNK - 1) { CP_WAIT0(); } else { CP_WAIT1(); }

        // ---- convert: LDS fp32 staging -> fp16 STS ----
        {
            char* dA = smem + ((s & 1) ? OFF_F1 : OFF_F0) + q * 8;
            #pragma unroll
            for (int g = 0; g < 8; g++) {
                float4 v = *(const float4*)(smem + (stg - sbase) + g * (8 * SPITCH));
                uint2 h;
                h.x = cvt2(v.x, v.y);
                h.y = cvt2(v.z, v.w);
                *(uint2*)(dA + (rg + g * 8) * APB) = h;
            }
        }
        __syncthreads();   // f16 buffer visible to all warps; staging reads done

        // ---- issue chunk s+2 into the staging buffer just consumed ----
        if (s + 2 < NCHUNK) {
            const int sn = s + 2;
            const int offs = ((sn >> 2) & 1) * (DD * DD) + ((sn >> 1) & 1) * DD + (sn & 1);
            #pragma unroll
            for (int g = 0; g < 8; g++)
                cp16(stg + g * (8 * SPITCH), src0[g] + (size_t)offs * CH);
            CP_COMMIT();
        }

        // ---- compute: 4 k16-steps, warp tile 32x32 ----
        #pragma unroll
        for (int kb = 0; kb < 4; kb++) {
            uint32_t a0[4], a1[4];
            ldm_x4(a0, fbase + aOff0 + kb * 32);
            ldm_x4(a1, fbase + aOff1 + kb * 32);

            uint2 w2[4];
            #pragma unroll
            for (int n = 0; n < 4; n++)
                w2[n] = __ldg(&wfrag[(((s * 4 + kb) * 8) + wn * 4 + n) * 32 + l]);

            #pragma unroll
            for (int n = 0; n < 4; n++) {
                mma_fp16(acc0[n], a0, (const uint32_t*)&w2[n]);
                mma_fp16(acc1[n], a1, (const uint32_t*)&w2[n]);
            }
        }
        __syncthreads();   // MMA reads done before next convert overwrites f16 buf
    }

    // ---- epilogue: streaming float2 stores ----
    const int r0 = blockIdx.x * MT + wm * 32 + (l >> 2);
    const int cb = wn * 32 + (l & 3) * 2;
    #pragma unroll
    for (int n = 0; n < 4; n++) {
        __stcs((float2*)&out[(size_t)r0 * 64 + cb + n * 8],        make_float2(acc0[n][0], acc0[n][1]));
        __stcs((float2*)&out[(size_t)(r0 + 8) * 64 + cb + n * 8],  make_float2(acc0[n][2], acc0[n][3]));
        __stcs((float2*)&out[(size_t)(r0 + 16) * 64 + cb + n * 8], make_float2(acc1[n][0], acc1[n][1]));
        __stcs((float2*)&out[(size_t)(r0 + 24) * 64 + cb + n * 8], make_float2(acc1[n][2], acc1[n][3]));
    }
}

extern "C" void kernel_launch(void* const* d_in, const int* in_sizes, int n_in,
                              void* d_out, int out_size) {
    const float* in_data = (const float*)d_in[0];
    // d_in[1] = ijk: canonical lexicographic order by construction -> unused
    const float* w_out   = (const float*)d_in[2];
    float*       out     = (float*)d_out;

    cudaFuncSetAttribute(ds_fp16_mma_kernel,
                         cudaFuncAttributeMaxDynamicSharedMemorySize, SMEM_TOTAL);
    conv_wf_kernel<<<64, 256>>>(w_out);
    ds_fp16_mma_kernel<<<NCTA, 128, SMEM_TOTAL>>>(in_data, out);
}

// round 14
// speedup vs baseline: 1.3174x; 1.3174x over previous
#include <cuda_runtime.h>
#include <cuda_fp16.h>
#include <cstdint>

// ---------------- problem constants ----------------
#define DD    96
#define DSC   48
#define CH    64
#define ND    (DSC*DSC*DSC)     // 110592 coarse voxels
#define MT    64                // M tile per CTA
#define NCTA  (ND/MT)           // 1728
#define NCHUNK 8

// A rows padded to 72 fp16 (144 B) for conflict-free ldmatrix
#define APITCH 72
#define APB    (APITCH*2)

// ---------------- smem layout (bytes) ----------------
#define SM_BROW 0                          // 64 ints
#define OFF_A0  512
#define OFF_A1  (OFF_A0 + MT*APB)          // +9216
#define SMEM_TOTAL (OFF_A1 + MT*APB)       // 18944

// W pre-packed in m16n8k16 B-fragment order:
// idx = (((s*4 + kb)*8 + jn)*32 + lane)*2 + r
// element: k = s*64 + kb*16 + r*8 + (lane%4)*2 + h,  n = jn*8 + lane/4
__device__ __align__(16) uint32_t g_wf[NCHUNK * 4 * 8 * 32 * 2];   // 64 KB

// ---------------- helpers ----------------
__device__ __forceinline__ uint32_t smem_u32(const void* p) {
    uint32_t a;
    asm("{ .reg .u64 t; cvta.to.shared.u64 t, %1; cvt.u32.u64 %0, t; }" : "=r"(a) : "l"(p));
    return a;
}
__device__ __forceinline__ void ldm_x4(uint32_t* r, uint32_t addr) {
    asm volatile("ldmatrix.sync.aligned.m8n8.x4.shared.b16 {%0,%1,%2,%3}, [%4];"
        : "=r"(r[0]), "=r"(r[1]), "=r"(r[2]), "=r"(r[3]) : "r"(addr));
}
__device__ __forceinline__ void mma_fp16(float* d, const uint32_t* a, const uint32_t* b) {
    asm volatile("mma.sync.aligned.m16n8k16.row.col.f32.f16.f16.f32 "
        "{%0,%1,%2,%3}, {%4,%5,%6,%7}, {%8,%9}, {%0,%1,%2,%3};"
        : "+f"(d[0]), "+f"(d[1]), "+f"(d[2]), "+f"(d[3])
        : "r"(a[0]), "r"(a[1]), "r"(a[2]), "r"(a[3]), "r"(b[0]), "r"(b[1]));
}
__device__ __forceinline__ uint32_t cvt2(float a, float b) {
    __half2 h = __floats2half2_rn(a, b);
    return *(uint32_t*)&h;
}
__device__ __forceinline__ void pf_l2(const void* p) {
    asm volatile("prefetch.global.L2 [%0];" :: "l"(p));
}

// ---------------- pre-kernel: W -> fp16 fragment-order ----------------
__global__ void conv_wf_kernel(const float* __restrict__ w) {
    int idx = blockIdx.x * blockDim.x + threadIdx.x;   // 0..16383
    int r  = idx & 1;
    int l  = (idx >> 1) & 31;
    int jn = (idx >> 6) & 7;
    int kb = (idx >> 9) & 3;
    int s  = idx >> 11;
    int k  = s * 64 + kb * 16 + r * 8 + (l & 3) * 2;
    int n  = jn * 8 + (l >> 2);
    g_wf[idx] = cvt2(w[k * 64 + n], w[(k + 1) * 64 + n]);
}

// ---------------- main kernel: 128 threads, 4 warps (2m x 2n), tile M32 x N32 ----
extern __shared__ char smem[];

__global__ void __launch_bounds__(128, 4)
ds_fp16_mma_kernel(const float* __restrict__ in_data, float* __restrict__ out) {
    const int tid = threadIdx.x;
    const int wid = tid >> 5;
    const int l   = tid & 31;
    const int wm  = wid & 1;      // m-tile of warp (rows wm*32..+32)
    const int wn  = wid >> 1;     // n-tile of warp (cols wn*32..+32)
    const uint32_t sbase = smem_u32(smem);

    int* baseRow = (int*)(smem + SM_BROW);
    if (tid < MT) {
        int dm  = blockIdx.x * MT + tid;
        int di  = dm / (DSC * DSC);
        int rem = dm - di * DSC * DSC;
        int dj  = rem / DSC;
        int dk  = rem - dj * DSC;
        baseRow[tid] = ((2 * di) * DD + 2 * dj) * DD + 2 * dk;
    }
    __syncthreads();

    // loader role: 16 threads per row, one float4 each -> fully coalesced lines
    const int q  = tid & 15;           // float4 index within 256B row
    const int rg = tid >> 4;           // 0..7; rows rg + g*8
    int rb[8];
    #pragma unroll
    for (int g = 0; g < 8; g++) rb[g] = baseRow[rg + g * 8];

    // ldmatrix A address components
    const uint32_t aOff0 = (uint32_t)((wm * 32 + (l & 15)) * APITCH + (l >> 4) * 8) * 2;
    const uint32_t aOff1 = aOff0 + 16 * APB;

    float acc0[4][4], acc1[4][4];
    #pragma unroll
    for (int n = 0; n < 4; n++)
        #pragma unroll
        for (int i = 0; i < 4; i++) { acc0[n][i] = 0.0f; acc1[n][i] = 0.0f; }

    // prefetch chunk 0 (octant 0: offs = 0), streaming loads (read-once data)
    float4 pf[8];
    #pragma unroll
    for (int g = 0; g < 8; g++)
        pf[g] = __ldcs((const float4*)(in_data + (size_t)rb[g] * CH + q * 4));

    const uint2* wfrag = (const uint2*)g_wf;   // index: ((s*4+kb)*8 + jn)*32 + lane

    for (int s = 0; s < NCHUNK; s++) {
        const uint32_t abase = sbase + ((s & 1) ? OFF_A1 : OFF_A0);

        // ---- fill: fp32->fp16 convert + STS.64 into buf[s&1] ----
        {
            char* dA = smem + ((s & 1) ? OFF_A1 : OFF_A0) + q * 8;
            #pragma unroll
            for (int g = 0; g < 8; g++) {
                uint2 h;
                h.x = cvt2(pf[g].x, pf[g].y);
                h.y = cvt2(pf[g].z, pf[g].w);
                *(uint2*)(dA + (rg + g * 8) * APB) = h;
            }
        }

        // ---- issue next chunk's demand loads BEFORE the barrier ----
        if (s + 1 < NCHUNK) {
            const int sn = s + 1;
            const int offs = ((sn >> 2) & 1) * (DD * DD) + ((sn >> 1) & 1) * DD + (sn & 1);
            #pragma unroll
            for (int g = 0; g < 8; g++)
                pf[g] = __ldcs((const float4*)(in_data + (size_t)(rb[g] + offs) * CH + q * 4));
        }

        // ---- L2 prefetch for chunk s+2: keeps DRAM busy through the MMAs ----
        if (s + 2 < NCHUNK) {
            const int sn = s + 2;
            const int offs = ((sn >> 2) & 1) * (DD * DD) + ((sn >> 1) & 1) * DD + (sn & 1);
            #pragma unroll
            for (int g = 0; g < 8; g++)
                pf_l2(in_data + (size_t)(rb[g] + offs) * CH + q * 4);
        }
        __syncthreads();   // single barrier per chunk (double buffered)

        // ---- compute: 4 k16-steps, warp tile 32x32 ----
        #pragma unroll
        for (int kb = 0; kb < 4; kb++) {
            uint32_t a0[4], a1[4];
            ldm_x4(a0, abase + aOff0 + kb * 32);
            ldm_x4(a1, abase + aOff1 + kb * 32);

            uint2 w2[4];
            #pragma unroll
            for (int n = 0; n < 4; n++)
                w2[n] = __ldg(&wfrag[(((s * 4 + kb) * 8) + wn * 4 + n) * 32 + l]);

            #pragma unroll
            for (int n = 0; n < 4; n++) {
                mma_fp16(acc0[n], a0, (const uint32_t*)&w2[n]);
                mma_fp16(acc1[n], a1, (const uint32_t*)&w2[n]);
            }
        }
    }

    // ---- epilogue: streaming float2 stores ----
    const int r0 = blockIdx.x * MT + wm * 32 + (l >> 2);
    const int cb = wn * 32 + (l & 3) * 2;
    #pragma unroll
    for (int n = 0; n < 4; n++) {
        __stcs((float2*)&out[(size_t)r0 * 64 + cb + n * 8],        make_float2(acc0[n][0], acc0[n][1]));
        __stcs((float2*)&out[(size_t)(r0 + 8) * 64 + cb + n * 8],  make_float2(acc0[n][2], acc0[n][3]));
        __stcs((float2*)&out[(size_t)(r0 + 16) * 64 + cb + n * 8], make_float2(acc1[n][0], acc1[n][1]));
        __stcs((float2*)&out[(size_t)(r0 + 24) * 64 + cb + n * 8], make_float2(acc1[n][2], acc1[n][3]));
    }
}

extern "C" void kernel_launch(void* const* d_in, const int* in_sizes, int n_in,
                              void* d_out, int out_size) {
    const float* in_data = (const float*)d_in[0];
    // d_in[1] = ijk: canonical lexicographic order by construction -> unused
    const float* w_out   = (const float*)d_in[2];
    float*       out     = (float*)d_out;

    cudaFuncSetAttribute(ds_fp16_mma_kernel,
                         cudaFuncAttributeMaxDynamicSharedMemorySize, SMEM_TOTAL);
    conv_wf_kernel<<<64, 256>>>(w_out);
    ds_fp16_mma_kernel<<<NCTA, 128, SMEM_TOTAL>>>(in_data, out);
}